// round 2
// baseline (speedup 1.0000x reference)
#include <cuda_runtime.h>
#include <cstdint>

#define B_   4
#define T_   4096
#define I_   1024
#define H_   16
#define D_   64
#define M_   (B_ * T_)        // 16384 rows (b,t)
#define NPH  128              // N per head: (d,k/v) interleaved
#define CH   128              // scan chunk length
#define NC   (T_ / CH)        // 32 chunks
#define NBH  (B_ * H_)        // 64 (b,h) pairs

// ---------------- scratch (device globals: allocation-free) ----------------
__device__ float g_v [ (size_t)M_ * H_ * D_ ];   // 64 MB: silu(v) in (bt, h, d)
__device__ float g_s [ (size_t)M_ * H_ ];        // 1 MB : scores (bt, h)
__device__ float g_am[ NBH * NC ];
__device__ float g_au[ NBH * NC ];
__device__ float g_aw[ NBH * NC * D_ ];
__device__ float g_pm[ NBH * NC ];
__device__ float g_pu[ NBH * NC ];
__device__ float g_pw[ NBH * NC * D_ ];

// ---------------------------------------------------------------------------
// Kernel 1: fused GEMM + silu + score + v-store.
//   C[128 x 128] tile = inputs[m0:m0+128, :] @ kv_kernel[:, h, :, :]
//   epilogue: silu; s[row] = sum_d q[h,d]*k; store v as (bt,h,d).
// ---------------------------------------------------------------------------
__global__ __launch_bounds__(256)
void k_gemm_silu(const float* __restrict__ inp,
                 const float* __restrict__ kvw,
                 const float* __restrict__ qw)
{
    __shared__ __align__(16) float As[2][16][132];
    __shared__ __align__(16) float Bs[2][16][132];
    __shared__ float sred[128][17];

    const int t  = threadIdx.x;          // 0..255
    const int tx = t & 15;               // col group
    const int ty = t >> 4;               // row group
    const int m0 = blockIdx.x * 128;
    const int h  = blockIdx.y;

    float acc[8][8];
#pragma unroll
    for (int i = 0; i < 8; i++)
#pragma unroll
        for (int j = 0; j < 8; j++) acc[i][j] = 0.f;

    float4 ra[2], rb[2];

    auto gload = [&](int kt) {
#pragma unroll
        for (int q = 0; q < 2; q++) {
            int L    = t + q * 256;
            int arow = L >> 2;
            int ac4  = L & 3;
            ra[q] = *(const float4*)(inp + (size_t)(m0 + arow) * I_ + kt * 16 + ac4 * 4);
        }
#pragma unroll
        for (int q = 0; q < 2; q++) {
            int L    = t + q * 256;
            int brow = L >> 5;
            int bc4  = L & 31;
            rb[q] = *(const float4*)(kvw + (size_t)(kt * 16 + brow) * (H_ * NPH)
                                         + h * NPH + bc4 * 4);
        }
    };

    auto sstore = [&](int buf) {
#pragma unroll
        for (int q = 0; q < 2; q++) {
            int L    = t + q * 256;
            int arow = L >> 2;
            int ac4  = L & 3;
            As[buf][ac4 * 4 + 0][arow] = ra[q].x;
            As[buf][ac4 * 4 + 1][arow] = ra[q].y;
            As[buf][ac4 * 4 + 2][arow] = ra[q].z;
            As[buf][ac4 * 4 + 3][arow] = ra[q].w;
        }
#pragma unroll
        for (int q = 0; q < 2; q++) {
            int L    = t + q * 256;
            int brow = L >> 5;
            int bc4  = L & 31;
            *(float4*)&Bs[buf][brow][bc4 * 4] = rb[q];
        }
    };

    auto compute = [&](int buf) {
#pragma unroll
        for (int k = 0; k < 16; k++) {
            float4 a0 = *(const float4*)&As[buf][k][ty * 8];
            float4 a1 = *(const float4*)&As[buf][k][ty * 8 + 4];
            float4 b0 = *(const float4*)&Bs[buf][k][tx * 8];
            float4 b1 = *(const float4*)&Bs[buf][k][tx * 8 + 4];
            float av[8] = {a0.x, a0.y, a0.z, a0.w, a1.x, a1.y, a1.z, a1.w};
            float bv[8] = {b0.x, b0.y, b0.z, b0.w, b1.x, b1.y, b1.z, b1.w};
#pragma unroll
            for (int i = 0; i < 8; i++)
#pragma unroll
                for (int j = 0; j < 8; j++)
                    acc[i][j] = fmaf(av[i], bv[j], acc[i][j]);
        }
    };

    const int NKT = I_ / 16;   // 64 k-tiles
    int buf = 0;
    gload(0);
    sstore(0);
    __syncthreads();
    for (int kt = 0; kt < NKT; kt++) {
        if (kt + 1 < NKT) gload(kt + 1);
        compute(buf);
        if (kt + 1 < NKT) sstore(buf ^ 1);
        buf ^= 1;
        __syncthreads();
    }

    // ---- epilogue: silu, score partials, v store ----
    const float q0 = qw[h * D_ + tx * 4 + 0];
    const float q1 = qw[h * D_ + tx * 4 + 1];
    const float q2 = qw[h * D_ + tx * 4 + 2];
    const float q3 = qw[h * D_ + tx * 4 + 3];

#pragma unroll
    for (int i = 0; i < 8; i++) {
#pragma unroll
        for (int j = 0; j < 8; j++) {
            float x = acc[i][j];
            acc[i][j] = __fdividef(x, 1.f + __expf(-x));   // silu
        }
        const int row = m0 + ty * 8 + i;
        float4 vv = make_float4(acc[i][1], acc[i][3], acc[i][5], acc[i][7]);
        *(float4*)&g_v[((size_t)row * H_ + h) * D_ + tx * 4] = vv;
        sred[ty * 8 + i][tx] = q0 * acc[i][0] + q1 * acc[i][2]
                             + q2 * acc[i][4] + q3 * acc[i][6];
    }
    __syncthreads();
    if (t < 128) {
        float s = 0.f;
#pragma unroll
        for (int j = 0; j < 16; j++) s += sred[t][j];
        g_s[(size_t)(m0 + t) * H_ + h] = s;
    }
}

// ---------------------------------------------------------------------------
// Kernel 2: per-chunk aggregates (reduction): m = max s, u = sum e, w = sum e*v
// grid (NC, NBH), block 64 (one thread per d)
// ---------------------------------------------------------------------------
__global__ __launch_bounds__(64)
void k_agg()
{
    const int c  = blockIdx.x;
    const int bh = blockIdx.y;
    const int b  = bh >> 4;
    const int h  = bh & 15;
    const int d  = threadIdx.x;
    const int t0 = c * CH;

    __shared__ float ssh[CH];
    __shared__ float esh[CH];

    for (int i = d; i < CH; i += 64)
        ssh[i] = g_s[(size_t)(b * T_ + t0 + i) * H_ + h];
    __syncthreads();

    float m = -1e30f;
#pragma unroll 8
    for (int i = 0; i < CH; i++) m = fmaxf(m, ssh[i]);

    for (int i = d; i < CH; i += 64) esh[i] = __expf(ssh[i] - m);
    __syncthreads();

    float u = 0.f, w = 0.f;
    const float* vp = g_v + ((size_t)(b * T_ + t0) * H_ + h) * D_ + d;
#pragma unroll 4
    for (int i = 0; i < CH; i++) {
        float e = esh[i];
        u += e;
        w = fmaf(e, vp[(size_t)i * (H_ * D_)], w);
    }

    const int idx = bh * NC + c;
    if (d == 0) { g_am[idx] = m; g_au[idx] = u; }
    g_aw[idx * D_ + d] = w;
}

// ---------------------------------------------------------------------------
// Kernel 3: exclusive prefix over chunk aggregates. grid NBH, block 64.
// ---------------------------------------------------------------------------
__global__ __launch_bounds__(64)
void k_prefix()
{
    const int bh = blockIdx.x;
    const int d  = threadIdx.x;
    float m = -1e30f, u = 0.f, w = 0.f;
    for (int c = 0; c < NC; c++) {
        const int idx = bh * NC + c;
        if (d == 0) { g_pm[idx] = m; g_pu[idx] = u; }
        g_pw[idx * D_ + d] = w;
        float am = g_am[idx];
        float au = g_au[idx];
        float aw = g_aw[idx * D_ + d];
        float mn = fmaxf(m, am);
        float ea = __expf(m  - mn);
        float eb = __expf(am - mn);
        u = u * ea + au * eb;
        w = w * ea + aw * eb;
        m = mn;
    }
}

// ---------------------------------------------------------------------------
// Kernel 4: apply — seed local inclusive scan with chunk prefix, emit w/u.
// grid (NC, NBH), block 64.
// ---------------------------------------------------------------------------
__global__ __launch_bounds__(64)
void k_apply(float* __restrict__ out)
{
    const int c  = blockIdx.x;
    const int bh = blockIdx.y;
    const int b  = bh >> 4;
    const int h  = bh & 15;
    const int d  = threadIdx.x;
    const int t0 = c * CH;

    __shared__ float ssh[CH];
    for (int i = d; i < CH; i += 64)
        ssh[i] = g_s[(size_t)(b * T_ + t0 + i) * H_ + h];
    __syncthreads();

    const int idx = bh * NC + c;
    float m = g_pm[idx];
    float u = g_pu[idx];
    float w = g_pw[idx * D_ + d];

    const float* vp = g_v + ((size_t)(b * T_ + t0) * H_ + h) * D_ + d;
    float*       op = out + ((size_t)(b * T_ + t0) * H_ + h) * D_ + d;

#pragma unroll 4
    for (int i = 0; i < CH; i++) {
        float s  = ssh[i];
        float mn = fmaxf(m, s);
        float ea = __expf(m - mn);
        float eb = __expf(s - mn);
        u = u * ea + eb;
        w = fmaf(w, ea, vp[(size_t)i * (H_ * D_)] * eb);
        m = mn;
        op[(size_t)i * (H_ * D_)] = __fdividef(w, u);
    }
}

// ---------------------------------------------------------------------------
extern "C" void kernel_launch(void* const* d_in, const int* in_sizes, int n_in,
                              void* d_out, int out_size)
{
    const float* inp = (const float*)d_in[0];   // (B,T,I)
    const float* kvw = (const float*)d_in[1];   // (I,H,D,2)
    const float* qw  = (const float*)d_in[2];   // (H,D)
    float* out = (float*)d_out;                 // (B,T,H,D)

    k_gemm_silu<<<dim3(M_ / 128, H_), 256>>>(inp, kvw, qw);
    k_agg   <<<dim3(NC, NBH), 64>>>();
    k_prefix<<<NBH, 64>>>();
    k_apply <<<dim3(NC, NBH), 64>>>(out);
}

// round 3
// speedup vs baseline: 2.7697x; 2.7697x over previous
#include <cuda_runtime.h>
#include <cuda_bf16.h>
#include <cstdint>

#define B_   4
#define T_   4096
#define I_   1024
#define H_   16
#define D_   64
#define M_   (B_ * T_)        // 16384 rows (b,t)
#define NTOT 2048             // total N columns = H * 128
#define CH   128              // scan chunk length
#define NC   (T_ / CH)        // 32 chunks
#define NBH  (B_ * H_)        // 64 (b,h) pairs

// ---------------- scratch (device globals: allocation-free) ----------------
__device__ float g_v [ (size_t)M_ * H_ * D_ ];   // 64 MB: silu(v) in (bt, h, d)
__device__ float g_s [ (size_t)M_ * H_ ];        // 1 MB : scores (bt, h)
__device__ float g_am[ NBH * NC ];
__device__ float g_au[ NBH * NC ];
__device__ float g_aw[ NBH * NC * D_ ];
__device__ float g_pm[ NBH * NC ];
__device__ float g_pu[ NBH * NC ];
__device__ float g_pw[ NBH * NC * D_ ];

// ---------------- mma helpers ----------------
__device__ __forceinline__ void ldsm_x4(uint32_t* r, const void* p) {
    uint32_t a = (uint32_t)__cvta_generic_to_shared(p);
    asm volatile("ldmatrix.sync.aligned.m8n8.x4.shared.b16 {%0,%1,%2,%3}, [%4];"
                 : "=r"(r[0]), "=r"(r[1]), "=r"(r[2]), "=r"(r[3]) : "r"(a));
}
__device__ __forceinline__ void ldsm_x2t(uint32_t* r, const void* p) {
    uint32_t a = (uint32_t)__cvta_generic_to_shared(p);
    asm volatile("ldmatrix.sync.aligned.m8n8.x2.trans.shared.b16 {%0,%1}, [%2];"
                 : "=r"(r[0]), "=r"(r[1]) : "r"(a));
}
__device__ __forceinline__ void mma16816(float* c, const uint32_t* a, const uint32_t* b) {
    asm volatile(
        "mma.sync.aligned.m16n8k16.row.col.f32.bf16.bf16.f32 "
        "{%0,%1,%2,%3}, {%4,%5,%6,%7}, {%8,%9}, {%0,%1,%2,%3};"
        : "+f"(c[0]), "+f"(c[1]), "+f"(c[2]), "+f"(c[3])
        : "r"(a[0]), "r"(a[1]), "r"(a[2]), "r"(a[3]), "r"(b[0]), "r"(b[1]));
}

// ---------------------------------------------------------------------------
// Kernel 1: split-bf16 tensor-core GEMM + silu + score + v-store.
// Tile 128 x 256 (2 heads), 8 warps (2x4), warp tile 64x64, k-step 16.
// ---------------------------------------------------------------------------
__global__ __launch_bounds__(256, 1)
void k_gemm_silu(const float* __restrict__ inp,
                 const float* __restrict__ kvw,
                 const float* __restrict__ qw)
{
    __shared__ __align__(16) unsigned short Ah[128][24];
    __shared__ __align__(16) unsigned short Al[128][24];
    __shared__ __align__(16) unsigned short Bh[16][264];
    __shared__ __align__(16) unsigned short Bl[16][264];
    __shared__ float sred[2][128][2];

    const int t    = threadIdx.x;
    const int warp = t >> 5, lane = t & 31;
    const int wm   = warp >> 2, wn = warp & 3;
    const int g    = lane >> 2, tg = lane & 3;
    const int m0   = blockIdx.x * 128;
    const int n0   = blockIdx.y * 256;

    float acc[4][8][4];
#pragma unroll
    for (int i = 0; i < 4; i++)
#pragma unroll
        for (int j = 0; j < 8; j++)
#pragma unroll
            for (int c = 0; c < 4; c++) acc[i][j][c] = 0.f;

    float4 ra[2], rb[4];

    auto gload = [&](int kt) {
#pragma unroll
        for (int q = 0; q < 2; q++) {
            int idx = t + q * 256;
            ra[q] = *(const float4*)(inp + (size_t)(m0 + (idx >> 2)) * I_
                                         + kt * 16 + (idx & 3) * 4);
        }
#pragma unroll
        for (int q = 0; q < 4; q++) {
            int idx = t + q * 256;
            rb[q] = *(const float4*)(kvw + (size_t)(kt * 16 + (idx >> 6)) * NTOT
                                         + n0 + (idx & 63) * 4);
        }
    };

    auto cvtstore = [&]() {
#pragma unroll
        for (int q = 0; q < 2; q++) {
            int idx = t + q * 256;
            int r = idx >> 2, c = (idx & 3) * 4;
            float x[4] = {ra[q].x, ra[q].y, ra[q].z, ra[q].w};
            uint32_t ph[2], pl[2];
#pragma unroll
            for (int p = 0; p < 2; p++) {
                unsigned short h0 = __bfloat16_as_ushort(__float2bfloat16(x[2*p]));
                unsigned short h1 = __bfloat16_as_ushort(__float2bfloat16(x[2*p+1]));
                float r0 = x[2*p]   - __bfloat162float(__ushort_as_bfloat16(h0));
                float r1 = x[2*p+1] - __bfloat162float(__ushort_as_bfloat16(h1));
                unsigned short l0 = __bfloat16_as_ushort(__float2bfloat16(r0));
                unsigned short l1 = __bfloat16_as_ushort(__float2bfloat16(r1));
                ph[p] = (uint32_t)h0 | ((uint32_t)h1 << 16);
                pl[p] = (uint32_t)l0 | ((uint32_t)l1 << 16);
            }
            *(uint2*)&Ah[r][c] = make_uint2(ph[0], ph[1]);
            *(uint2*)&Al[r][c] = make_uint2(pl[0], pl[1]);
        }
#pragma unroll
        for (int q = 0; q < 4; q++) {
            int idx = t + q * 256;
            int r = idx >> 6, c = (idx & 63) * 4;
            float x[4] = {rb[q].x, rb[q].y, rb[q].z, rb[q].w};
            uint32_t ph[2], pl[2];
#pragma unroll
            for (int p = 0; p < 2; p++) {
                unsigned short h0 = __bfloat16_as_ushort(__float2bfloat16(x[2*p]));
                unsigned short h1 = __bfloat16_as_ushort(__float2bfloat16(x[2*p+1]));
                float r0 = x[2*p]   - __bfloat162float(__ushort_as_bfloat16(h0));
                float r1 = x[2*p+1] - __bfloat162float(__ushort_as_bfloat16(h1));
                unsigned short l0 = __bfloat16_as_ushort(__float2bfloat16(r0));
                unsigned short l1 = __bfloat16_as_ushort(__float2bfloat16(r1));
                ph[p] = (uint32_t)h0 | ((uint32_t)h1 << 16);
                pl[p] = (uint32_t)l0 | ((uint32_t)l1 << 16);
            }
            *(uint2*)&Bh[r][c] = make_uint2(ph[0], ph[1]);
            *(uint2*)&Bl[r][c] = make_uint2(pl[0], pl[1]);
        }
    };

    const int arow = lane & 15;
    const int acol = (lane >> 4) * 8;

    gload(0);
    for (int kt = 0; kt < I_ / 16; kt++) {
        cvtstore();
        __syncthreads();
        if (kt + 1 < I_ / 16) gload(kt + 1);

        uint32_t afh[4][4], afl[4][4];
#pragma unroll
        for (int it = 0; it < 4; it++) {
            ldsm_x4(afh[it], &Ah[wm * 64 + it * 16 + arow][acol]);
            ldsm_x4(afl[it], &Al[wm * 64 + it * 16 + arow][acol]);
        }
#pragma unroll
        for (int jt = 0; jt < 8; jt++) {
            uint32_t bfh[2], bfl[2];
            ldsm_x2t(bfh, &Bh[arow][wn * 64 + jt * 8]);
            ldsm_x2t(bfl, &Bl[arow][wn * 64 + jt * 8]);
#pragma unroll
            for (int it = 0; it < 4; it++) {
                mma16816(acc[it][jt], afh[it], bfh);
                mma16816(acc[it][jt], afh[it], bfl);
                mma16816(acc[it][jt], afl[it], bfh);
            }
        }
        __syncthreads();
    }

    // ---- epilogue: silu, v store, score reduce ----
#pragma unroll
    for (int it = 0; it < 4; it++)
#pragma unroll
        for (int jt = 0; jt < 8; jt++)
#pragma unroll
            for (int c = 0; c < 4; c++) {
                float x = acc[it][jt][c];
                acc[it][jt][c] = __fdividef(x, 1.f + __expf(-x));
            }

    const int head_l = wn >> 1;               // 0 or 1 within block
    const int head_g = blockIdx.y * 2 + head_l;
    float ps[4][2];
#pragma unroll
    for (int it = 0; it < 4; it++) { ps[it][0] = 0.f; ps[it][1] = 0.f; }

#pragma unroll
    for (int it = 0; it < 4; it++) {
        const int row0 = m0 + wm * 64 + it * 16 + g;
#pragma unroll
        for (int jt = 0; jt < 8; jt++) {
            const int d  = (wn & 1) * 32 + jt * 4 + tg;
            const float qv = qw[head_g * D_ + d];
            ps[it][0] += qv * acc[it][jt][0];
            ps[it][1] += qv * acc[it][jt][2];
            g_v[((size_t)row0       * H_ + head_g) * D_ + d] = acc[it][jt][1];
            g_v[((size_t)(row0 + 8) * H_ + head_g) * D_ + d] = acc[it][jt][3];
        }
    }
    // reduce over tg (lanes xor 1, xor 2)
#pragma unroll
    for (int it = 0; it < 4; it++)
#pragma unroll
        for (int hhalf = 0; hhalf < 2; hhalf++) {
            float v = ps[it][hhalf];
            v += __shfl_xor_sync(0xffffffffu, v, 1);
            v += __shfl_xor_sync(0xffffffffu, v, 2);
            ps[it][hhalf] = v;
        }
    if (tg == 0) {
#pragma unroll
        for (int it = 0; it < 4; it++) {
            sred[head_l][wm * 64 + it * 16 + g    ][wn & 1] = ps[it][0];
            sred[head_l][wm * 64 + it * 16 + g + 8][wn & 1] = ps[it][1];
        }
    }
    __syncthreads();
    {
        const int hl  = t >> 7;
        const int row = t & 127;
        float s = sred[hl][row][0] + sred[hl][row][1];
        g_s[(size_t)(m0 + row) * H_ + blockIdx.y * 2 + hl] = s;
    }
}

// ---------------------------------------------------------------------------
// Kernel 2: per-chunk aggregates (reduction): m = max s, u = sum e, w = sum e*v
// ---------------------------------------------------------------------------
__global__ __launch_bounds__(64)
void k_agg()
{
    const int c  = blockIdx.x;
    const int bh = blockIdx.y;
    const int b  = bh >> 4;
    const int h  = bh & 15;
    const int d  = threadIdx.x;
    const int t0 = c * CH;

    __shared__ float ssh[CH];
    __shared__ float esh[CH];

    for (int i = d; i < CH; i += 64)
        ssh[i] = g_s[(size_t)(b * T_ + t0 + i) * H_ + h];
    __syncthreads();

    float m = -1e30f;
#pragma unroll 8
    for (int i = 0; i < CH; i++) m = fmaxf(m, ssh[i]);

    for (int i = d; i < CH; i += 64) esh[i] = __expf(ssh[i] - m);
    __syncthreads();

    float u = 0.f, w = 0.f;
    const float* vp = g_v + ((size_t)(b * T_ + t0) * H_ + h) * D_ + d;
#pragma unroll 4
    for (int i = 0; i < CH; i++) {
        float e = esh[i];
        u += e;
        w = fmaf(e, vp[(size_t)i * (H_ * D_)], w);
    }

    const int idx = bh * NC + c;
    if (d == 0) { g_am[idx] = m; g_au[idx] = u; }
    g_aw[idx * D_ + d] = w;
}

// ---------------------------------------------------------------------------
// Kernel 3: exclusive prefix over chunk aggregates.
// ---------------------------------------------------------------------------
__global__ __launch_bounds__(64)
void k_prefix()
{
    const int bh = blockIdx.x;
    const int d  = threadIdx.x;
    float m = -1e30f, u = 0.f, w = 0.f;
    for (int c = 0; c < NC; c++) {
        const int idx = bh * NC + c;
        if (d == 0) { g_pm[idx] = m; g_pu[idx] = u; }
        g_pw[idx * D_ + d] = w;
        float am = g_am[idx];
        float au = g_au[idx];
        float aw = g_aw[idx * D_ + d];
        float mn = fmaxf(m, am);
        float ea = __expf(m  - mn);
        float eb = __expf(am - mn);
        u = u * ea + au * eb;
        w = w * ea + aw * eb;
        m = mn;
    }
}

// ---------------------------------------------------------------------------
// Kernel 4: apply — seed local inclusive scan with chunk prefix, emit w/u.
// ---------------------------------------------------------------------------
__global__ __launch_bounds__(64)
void k_apply(float* __restrict__ out)
{
    const int c  = blockIdx.x;
    const int bh = blockIdx.y;
    const int b  = bh >> 4;
    const int h  = bh & 15;
    const int d  = threadIdx.x;
    const int t0 = c * CH;

    __shared__ float ssh[CH];
    for (int i = d; i < CH; i += 64)
        ssh[i] = g_s[(size_t)(b * T_ + t0 + i) * H_ + h];
    __syncthreads();

    const int idx = bh * NC + c;
    float m = g_pm[idx];
    float u = g_pu[idx];
    float w = g_pw[idx * D_ + d];

    const float* vp = g_v + ((size_t)(b * T_ + t0) * H_ + h) * D_ + d;
    float*       op = out + ((size_t)(b * T_ + t0) * H_ + h) * D_ + d;

#pragma unroll 4
    for (int i = 0; i < CH; i++) {
        float s  = ssh[i];
        float mn = fmaxf(m, s);
        float ea = __expf(m - mn);
        float eb = __expf(s - mn);
        u = u * ea + eb;
        w = fmaf(w, ea, vp[(size_t)i * (H_ * D_)] * eb);
        m = mn;
        op[(size_t)i * (H_ * D_)] = __fdividef(w, u);
    }
}

// ---------------------------------------------------------------------------
extern "C" void kernel_launch(void* const* d_in, const int* in_sizes, int n_in,
                              void* d_out, int out_size)
{
    const float* inp = (const float*)d_in[0];   // (B,T,I)
    const float* kvw = (const float*)d_in[1];   // (I,H,D,2)
    const float* qw  = (const float*)d_in[2];   // (H,D)
    float* out = (float*)d_out;                 // (B,T,H,D)

    k_gemm_silu<<<dim3(M_ / 128, NTOT / 256), 256>>>(inp, kvw, qw);
    k_agg   <<<dim3(NC, NBH), 64>>>();
    k_prefix<<<NBH, 64>>>();
    k_apply <<<dim3(NC, NBH), 64>>>(out);
}

// round 4
// speedup vs baseline: 3.2890x; 1.1875x over previous
#include <cuda_runtime.h>
#include <cuda_bf16.h>
#include <cstdint>

#define B_   4
#define T_   4096
#define I_   1024
#define H_   16
#define D_   64
#define M_   (B_ * T_)        // 16384 rows (b,t)
#define NTOT 2048             // total N columns = H * 128
#define CH   64               // scan chunk length
#define NC   (T_ / CH)        // 64 chunks
#define NBH  (B_ * H_)        // 64 (b,h) pairs

typedef unsigned short ushort_t;

// ---------------- scratch (device globals: allocation-free) ----------------
__device__ __align__(16) ushort_t g_ah[(size_t)M_ * I_];   // 32 MB
__device__ __align__(16) ushort_t g_al[(size_t)M_ * I_];   // 32 MB
__device__ __align__(16) ushort_t g_bh[(size_t)I_ * NTOT]; // 4 MB
__device__ __align__(16) ushort_t g_bl[(size_t)I_ * NTOT]; // 4 MB
__device__ __align__(16) float g_v [ (size_t)M_ * H_ * D_ ]; // 64 MB
__device__ __align__(16) float g_s [ (size_t)M_ * H_ ];      // 1 MB
__device__ float g_am[ NBH * NC ];
__device__ float g_au[ NBH * NC ];
__device__ float g_aw[ NBH * NC * D_ ];
__device__ float g_pm[ NBH * NC ];
__device__ float g_pu[ NBH * NC ];
__device__ float g_pw[ NBH * NC * D_ ];

// ---------------- helpers ----------------
__device__ __forceinline__ void split1(float x, ushort_t& h, ushort_t& l) {
    h = __bfloat16_as_ushort(__float2bfloat16(x));
    float r = x - __bfloat162float(__ushort_as_bfloat16(h));
    l = __bfloat16_as_ushort(__float2bfloat16(r));
}
__device__ __forceinline__ void ldsm_x4(uint32_t* r, const void* p) {
    uint32_t a = (uint32_t)__cvta_generic_to_shared(p);
    asm volatile("ldmatrix.sync.aligned.m8n8.x4.shared.b16 {%0,%1,%2,%3}, [%4];"
                 : "=r"(r[0]), "=r"(r[1]), "=r"(r[2]), "=r"(r[3]) : "r"(a));
}
__device__ __forceinline__ void ldsm_x2t(uint32_t* r, const void* p) {
    uint32_t a = (uint32_t)__cvta_generic_to_shared(p);
    asm volatile("ldmatrix.sync.aligned.m8n8.x2.trans.shared.b16 {%0,%1}, [%2];"
                 : "=r"(r[0]), "=r"(r[1]) : "r"(a));
}
__device__ __forceinline__ void mma16816(float* c, const uint32_t* a, const uint32_t* b) {
    asm volatile(
        "mma.sync.aligned.m16n8k16.row.col.f32.bf16.bf16.f32 "
        "{%0,%1,%2,%3}, {%4,%5,%6,%7}, {%8,%9}, {%0,%1,%2,%3};"
        : "+f"(c[0]), "+f"(c[1]), "+f"(c[2]), "+f"(c[3])
        : "r"(a[0]), "r"(a[1]), "r"(a[2]), "r"(a[3]), "r"(b[0]), "r"(b[1]));
}
__device__ __forceinline__ void cpa16(void* dst, const void* src) {
    uint32_t d = (uint32_t)__cvta_generic_to_shared(dst);
    asm volatile("cp.async.cg.shared.global [%0], [%1], 16;" :: "r"(d), "l"(src));
}
__device__ __forceinline__ void cpa_commit() { asm volatile("cp.async.commit_group;"); }
__device__ __forceinline__ void cpa_wait0()  { asm volatile("cp.async.wait_group 0;"); }

// ---------------------------------------------------------------------------
// Kernel 0: one-time fp32 -> (bf16 hi, bf16 lo) split of A and B.
// ---------------------------------------------------------------------------
#define NA4 ((size_t)M_ * I_ / 4)
#define NB4 ((size_t)I_ * NTOT / 4)
__global__ __launch_bounds__(256)
void k_split(const float* __restrict__ inp, const float* __restrict__ kvw)
{
    size_t i = (size_t)blockIdx.x * 256 + threadIdx.x;
    float4 x;
    ushort_t* dh;
    ushort_t* dl;
    size_t o;
    if (i < NA4)            { x = ((const float4*)inp)[i];       dh = g_ah; dl = g_al; o = i; }
    else if (i < NA4 + NB4) { o = i - NA4; x = ((const float4*)kvw)[o]; dh = g_bh; dl = g_bl; }
    else return;
    ushort_t h[4], l[4];
    split1(x.x, h[0], l[0]); split1(x.y, h[1], l[1]);
    split1(x.z, h[2], l[2]); split1(x.w, h[3], l[3]);
    uint2 ph = make_uint2((uint32_t)h[0] | ((uint32_t)h[1] << 16),
                          (uint32_t)h[2] | ((uint32_t)h[3] << 16));
    uint2 pl = make_uint2((uint32_t)l[0] | ((uint32_t)l[1] << 16),
                          (uint32_t)l[2] | ((uint32_t)l[3] << 16));
    ((uint2*)dh)[o] = ph;
    ((uint2*)dl)[o] = pl;
}

// ---------------------------------------------------------------------------
// Kernel 1: bf16 tensor-core GEMM (3-pass split) + silu + score + v-store
//           + fused per-chunk scan aggregates (CH=64: wm half == chunk).
// Tile 128x256 (2 heads), 8 warps (2x4), k-step 16, cp.async double buffer.
// ---------------------------------------------------------------------------
struct GSmem {
    ushort_t Ah[2][128][24];
    ushort_t Al[2][128][24];
    ushort_t Bh[2][16][264];
    ushort_t Bl[2][16][264];
    float sred[2][128][2];
    float s_sh[2][128];
    float e_sh[2][128];
    float w_sh[2][2][64];
    float m_sh[2][2];
    float u_sh[2][2];
};

__global__ __launch_bounds__(256, 1)
void k_gemm_silu(const float* __restrict__ qw)
{
    extern __shared__ __align__(16) char smem_raw[];
    GSmem& S = *reinterpret_cast<GSmem*>(smem_raw);

    const int t    = threadIdx.x;
    const int warp = t >> 5, lane = t & 31;
    const int wm   = warp >> 2, wn = warp & 3;
    const int g    = lane >> 2, tg = lane & 3;
    const int m0   = blockIdx.x * 128;
    const int n0   = blockIdx.y * 256;

    float acc[4][8][4];
#pragma unroll
    for (int i = 0; i < 4; i++)
#pragma unroll
        for (int j = 0; j < 8; j++)
#pragma unroll
            for (int c = 0; c < 4; c++) acc[i][j][c] = 0.f;

    // async tile load: A 128x16 (1 uint4/thread/plane), B 16x256 (2/plane)
    auto gload = [&](int kt, int buf) {
        {
            int row = t >> 1, c8 = (t & 1) * 8;
            size_t go = (size_t)(m0 + row) * I_ + kt * 16 + c8;
            cpa16(&S.Ah[buf][row][c8], &g_ah[go]);
            cpa16(&S.Al[buf][row][c8], &g_al[go]);
        }
#pragma unroll
        for (int q = 0; q < 2; q++) {
            int idx = t + q * 256;
            int row = idx >> 5, c8 = (idx & 31) * 8;
            size_t go = (size_t)(kt * 16 + row) * NTOT + n0 + c8;
            cpa16(&S.Bh[buf][row][c8], &g_bh[go]);
            cpa16(&S.Bl[buf][row][c8], &g_bl[go]);
        }
        cpa_commit();
    };

    const int arow = lane & 15;
    const int acol = (lane >> 4) * 8;

    gload(0, 0);
    cpa_wait0();
    __syncthreads();

    int buf = 0;
    const int NKT = I_ / 16;
    for (int kt = 0; kt < NKT; kt++) {
        if (kt + 1 < NKT) gload(kt + 1, buf ^ 1);

        uint32_t afh[4][4], afl[4][4];
#pragma unroll
        for (int it = 0; it < 4; it++) {
            ldsm_x4(afh[it], &S.Ah[buf][wm * 64 + it * 16 + arow][acol]);
            ldsm_x4(afl[it], &S.Al[buf][wm * 64 + it * 16 + arow][acol]);
        }
#pragma unroll
        for (int jt = 0; jt < 8; jt++) {
            uint32_t bfh[2], bfl[2];
            ldsm_x2t(bfh, &S.Bh[buf][arow][wn * 64 + jt * 8]);
            ldsm_x2t(bfl, &S.Bl[buf][arow][wn * 64 + jt * 8]);
#pragma unroll
            for (int it = 0; it < 4; it++) {
                mma16816(acc[it][jt], afh[it], bfh);
                mma16816(acc[it][jt], afh[it], bfl);
                mma16816(acc[it][jt], afl[it], bfh);
            }
        }
        if (kt + 1 < NKT) cpa_wait0();
        __syncthreads();
        buf ^= 1;
    }

    // ---- epilogue: silu, v store, score partials ----
#pragma unroll
    for (int it = 0; it < 4; it++)
#pragma unroll
        for (int jt = 0; jt < 8; jt++)
#pragma unroll
            for (int c = 0; c < 4; c++) {
                float x = acc[it][jt][c];
                acc[it][jt][c] = __fdividef(x, 1.f + __expf(-x));
            }

    const int head_l = wn >> 1;
    const int head_g = blockIdx.y * 2 + head_l;
    float ps[4][2];
#pragma unroll
    for (int it = 0; it < 4; it++) { ps[it][0] = 0.f; ps[it][1] = 0.f; }

#pragma unroll
    for (int it = 0; it < 4; it++) {
        const int row0 = m0 + wm * 64 + it * 16 + g;
#pragma unroll
        for (int jt = 0; jt < 8; jt++) {
            const int d  = (wn & 1) * 32 + jt * 4 + tg;
            const float qv = qw[head_g * D_ + d];
            ps[it][0] += qv * acc[it][jt][0];
            ps[it][1] += qv * acc[it][jt][2];
            g_v[((size_t)row0       * H_ + head_g) * D_ + d] = acc[it][jt][1];
            g_v[((size_t)(row0 + 8) * H_ + head_g) * D_ + d] = acc[it][jt][3];
        }
    }
#pragma unroll
    for (int it = 0; it < 4; it++)
#pragma unroll
        for (int hh = 0; hh < 2; hh++) {
            float v = ps[it][hh];
            v += __shfl_xor_sync(0xffffffffu, v, 1);
            v += __shfl_xor_sync(0xffffffffu, v, 2);
            ps[it][hh] = v;
        }
    if (tg == 0) {
#pragma unroll
        for (int it = 0; it < 4; it++) {
            S.sred[head_l][wm * 64 + it * 16 + g    ][wn & 1] = ps[it][0];
            S.sred[head_l][wm * 64 + it * 16 + g + 8][wn & 1] = ps[it][1];
        }
    }
    __syncthreads();

    // s per (head, row)
    {
        const int hl  = t >> 7;
        const int row = t & 127;
        float s = S.sred[hl][row][0] + S.sred[hl][row][1];
        g_s[(size_t)(m0 + row) * H_ + blockIdx.y * 2 + hl] = s;
        S.s_sh[hl][row] = s;
    }
    __syncthreads();

    // per-chunk (64-row half) max + expsum: warps 0,1 (one head each)
    if (warp < 2) {
#pragma unroll
        for (int half = 0; half < 2; half++) {
            float s0 = S.s_sh[warp][half * 64 + lane];
            float s1 = S.s_sh[warp][half * 64 + 32 + lane];
            float mx = fmaxf(s0, s1);
#pragma unroll
            for (int o = 16; o >= 1; o >>= 1)
                mx = fmaxf(mx, __shfl_xor_sync(0xffffffffu, mx, o));
            float e0 = __expf(s0 - mx);
            float e1 = __expf(s1 - mx);
            S.e_sh[warp][half * 64 + lane]      = e0;
            S.e_sh[warp][half * 64 + 32 + lane] = e1;
            float us = e0 + e1;
#pragma unroll
            for (int o = 16; o >= 1; o >>= 1)
                us += __shfl_xor_sync(0xffffffffu, us, o);
            if (lane == 0) { S.m_sh[warp][half] = mx; S.u_sh[warp][half] = us; }
        }
    }
    __syncthreads();

    // chunk w: each warp covers rows wm*64..+63 == chunk half wm
    {
        float pw[8];
#pragma unroll
        for (int jt = 0; jt < 8; jt++) pw[jt] = 0.f;
#pragma unroll
        for (int it = 0; it < 4; it++) {
            const int r0 = wm * 64 + it * 16 + g;
            float e0 = S.e_sh[head_l][r0];
            float e1 = S.e_sh[head_l][r0 + 8];
#pragma unroll
            for (int jt = 0; jt < 8; jt++)
                pw[jt] = fmaf(e0, acc[it][jt][1], fmaf(e1, acc[it][jt][3], pw[jt]));
        }
#pragma unroll
        for (int jt = 0; jt < 8; jt++) {
            float v = pw[jt];
            v += __shfl_xor_sync(0xffffffffu, v, 4);
            v += __shfl_xor_sync(0xffffffffu, v, 8);
            v += __shfl_xor_sync(0xffffffffu, v, 16);
            pw[jt] = v;
        }
        if (g == 0) {
#pragma unroll
            for (int jt = 0; jt < 8; jt++)
                S.w_sh[head_l][wm][(wn & 1) * 32 + jt * 4 + tg] = pw[jt];
        }
    }
    __syncthreads();

    // write chunk aggregates
    {
        const int hl   = t >> 7;
        const int half = (t >> 6) & 1;
        const int d    = t & 63;
        const int hg   = blockIdx.y * 2 + hl;
        const int b    = m0 >> 12;
        const int cb   = (m0 & 4095) >> 6;
        const int idx  = (b * H_ + hg) * NC + cb + half;
        g_aw[idx * D_ + d] = S.w_sh[hl][half][d];
        if (d == 0) { g_am[idx] = S.m_sh[hl][half]; g_au[idx] = S.u_sh[hl][half]; }
    }
}

// ---------------------------------------------------------------------------
// Kernel 3: exclusive prefix over chunk aggregates.
// ---------------------------------------------------------------------------
__global__ __launch_bounds__(64)
void k_prefix()
{
    const int bh = blockIdx.x;
    const int d  = threadIdx.x;
    float m = -1e30f, u = 0.f, w = 0.f;
    for (int c = 0; c < NC; c++) {
        const int idx = bh * NC + c;
        if (d == 0) { g_pm[idx] = m; g_pu[idx] = u; }
        g_pw[idx * D_ + d] = w;
        float am = g_am[idx];
        float au = g_au[idx];
        float aw = g_aw[idx * D_ + d];
        float mn = fmaxf(m, am);
        float ea = __expf(m  - mn);
        float eb = __expf(am - mn);
        u = u * ea + au * eb;
        w = w * ea + aw * eb;
        m = mn;
    }
}

// ---------------------------------------------------------------------------
// Kernel 4: apply — 4 heads per block (256 threads), CH=64.
// ---------------------------------------------------------------------------
__global__ __launch_bounds__(256)
void k_apply(float* __restrict__ out)
{
    const int c   = blockIdx.x;
    const int bh0 = blockIdx.y * 4;
    const int t   = threadIdx.x;
    const int hh  = t >> 6;
    const int d   = t & 63;
    const int bh  = bh0 + hh;
    const int b   = bh >> 4;
    const int h   = bh & 15;
    const int t0  = c * CH;

    __shared__ float ssh[4][CH];
    {
        const int i  = t >> 2;
        const int hx = t & 3;
        ssh[hx][i] = g_s[(size_t)(b * T_ + t0 + i) * H_ + ((bh0 + hx) & 15)];
    }
    __syncthreads();

    const int idx = bh * NC + c;
    float m = g_pm[idx];
    float u = g_pu[idx];
    float w = g_pw[idx * D_ + d];

    const float* vp = g_v + ((size_t)(b * T_ + t0) * H_ + h) * D_ + d;
    float*       op = out + ((size_t)(b * T_ + t0) * H_ + h) * D_ + d;

#pragma unroll 4
    for (int i = 0; i < CH; i++) {
        float s  = ssh[hh][i];
        float mn = fmaxf(m, s);
        float ea = __expf(m - mn);
        float eb = __expf(s - mn);
        u = u * ea + eb;
        w = fmaf(w, ea, vp[(size_t)i * (H_ * D_)] * eb);
        m = mn;
        op[(size_t)i * (H_ * D_)] = __fdividef(w, u);
    }
}

// ---------------------------------------------------------------------------
extern "C" void kernel_launch(void* const* d_in, const int* in_sizes, int n_in,
                              void* d_out, int out_size)
{
    const float* inp = (const float*)d_in[0];   // (B,T,I)
    const float* kvw = (const float*)d_in[1];   // (I,H,D,2)
    const float* qw  = (const float*)d_in[2];   // (H,D)
    float* out = (float*)d_out;                 // (B,T,H,D)

    static int smem_set = 0;
    if (!smem_set) {
        cudaFuncSetAttribute(k_gemm_silu,
                             cudaFuncAttributeMaxDynamicSharedMemorySize,
                             (int)sizeof(GSmem));
        smem_set = 1;
    }

    const int nsplit = (int)((NA4 + NB4 + 255) / 256);
    k_split<<<nsplit, 256>>>(inp, kvw);
    k_gemm_silu<<<dim3(M_ / 128, NTOT / 256), 256, sizeof(GSmem)>>>(qw);
    k_prefix<<<NBH, 64>>>();
    k_apply <<<dim3(NC, NBH / 4), 256>>>(out);
}

// round 7
// speedup vs baseline: 3.5139x; 1.0684x over previous
#include <cuda_runtime.h>
#include <cuda_bf16.h>
#include <cstdint>

#define B_   4
#define T_   4096
#define I_   1024
#define H_   16
#define D_   64
#define M_   (B_ * T_)        // 16384 rows (b,t)
#define NTOT 2048             // total N columns = H * 128
#define CH   64               // scan chunk length
#define NC   (T_ / CH)        // 64 chunks
#define NBH  (B_ * H_)        // 64 (b,h) pairs

#define KC   32               // K per pipeline stage
#define NST  (I_ / KC)        // 32 stages
#define STG  3                // ring depth

typedef unsigned short ushort_t;

// ---------------- scratch (device globals: allocation-free) ----------------
__device__ __align__(16) ushort_t g_ah[(size_t)M_ * I_];   // 32 MB
__device__ __align__(16) ushort_t g_al[(size_t)M_ * I_];   // 32 MB
__device__ __align__(16) ushort_t g_bh[(size_t)I_ * NTOT]; // 4 MB  [K][N]
__device__ __align__(16) ushort_t g_bl[(size_t)I_ * NTOT]; // 4 MB
__device__ __align__(16) float g_v [ (size_t)M_ * H_ * D_ ]; // 64 MB
__device__ __align__(16) float g_s [ (size_t)M_ * H_ ];      // 1 MB
__device__ float g_am[ NBH * NC ];
__device__ float g_au[ NBH * NC ];
__device__ float g_aw[ NBH * NC * D_ ];
__device__ float g_pm[ NBH * NC ];
__device__ float g_pu[ NBH * NC ];
__device__ float g_pw[ NBH * NC * D_ ];

// ---------------- helpers ----------------
__device__ __forceinline__ void split1(float x, ushort_t& h, ushort_t& l) {
    h = __bfloat16_as_ushort(__float2bfloat16(x));
    float r = x - __bfloat162float(__ushort_as_bfloat16(h));
    l = __bfloat16_as_ushort(__float2bfloat16(r));
}
__device__ __forceinline__ void ldsm_x4(uint32_t* r, const void* p) {
    uint32_t a = (uint32_t)__cvta_generic_to_shared(p);
    asm volatile("ldmatrix.sync.aligned.m8n8.x4.shared.b16 {%0,%1,%2,%3}, [%4];"
                 : "=r"(r[0]), "=r"(r[1]), "=r"(r[2]), "=r"(r[3]) : "r"(a));
}
__device__ __forceinline__ void ldsm_x2t(uint32_t* r, const void* p) {
    uint32_t a = (uint32_t)__cvta_generic_to_shared(p);
    asm volatile("ldmatrix.sync.aligned.m8n8.x2.trans.shared.b16 {%0,%1}, [%2];"
                 : "=r"(r[0]), "=r"(r[1]) : "r"(a));
}
__device__ __forceinline__ void mma16816(float* c, const uint32_t* a, const uint32_t* b) {
    asm volatile(
        "mma.sync.aligned.m16n8k16.row.col.f32.bf16.bf16.f32 "
        "{%0,%1,%2,%3}, {%4,%5,%6,%7}, {%8,%9}, {%0,%1,%2,%3};"
        : "+f"(c[0]), "+f"(c[1]), "+f"(c[2]), "+f"(c[3])
        : "r"(a[0]), "r"(a[1]), "r"(a[2]), "r"(a[3]), "r"(b[0]), "r"(b[1]));
}
__device__ __forceinline__ void cpa16(void* dst, const void* src) {
    uint32_t d = (uint32_t)__cvta_generic_to_shared(dst);
    asm volatile("cp.async.cg.shared.global [%0], [%1], 16;" :: "r"(d), "l"(src));
}

// ---------------------------------------------------------------------------
// Kernel 0: one-time fp32 -> (bf16 hi, bf16 lo) split of A and B.
// ---------------------------------------------------------------------------
#define NA4 ((size_t)M_ * I_ / 4)
#define NB4 ((size_t)I_ * NTOT / 4)
__global__ __launch_bounds__(256)
void k_split(const float* __restrict__ inp, const float* __restrict__ kvw)
{
    size_t i = (size_t)blockIdx.x * 256 + threadIdx.x;
    float4 x;
    ushort_t* dh;
    ushort_t* dl;
    size_t o;
    if (i < NA4)            { x = ((const float4*)inp)[i];       dh = g_ah; dl = g_al; o = i; }
    else if (i < NA4 + NB4) { o = i - NA4; x = ((const float4*)kvw)[o]; dh = g_bh; dl = g_bl; }
    else return;
    ushort_t h[4], l[4];
    split1(x.x, h[0], l[0]); split1(x.y, h[1], l[1]);
    split1(x.z, h[2], l[2]); split1(x.w, h[3], l[3]);
    ((uint2*)dh)[o] = make_uint2((uint32_t)h[0] | ((uint32_t)h[1] << 16),
                                 (uint32_t)h[2] | ((uint32_t)h[3] << 16));
    ((uint2*)dl)[o] = make_uint2((uint32_t)l[0] | ((uint32_t)l[1] << 16),
                                 (uint32_t)l[2] | ((uint32_t)l[3] << 16));
}

// ---------------------------------------------------------------------------
// Kernel 1: bf16 mma.sync GEMM (3-pass split) + silu + score + v-store
//           + fused per-chunk scan aggregates.
// Tile 128x256 (2 heads), 8 warps (2x4), KC=32, 3-stage cp.async ring.
// ---------------------------------------------------------------------------
struct GSmem {
    ushort_t Ah[STG][128][40];   // 30720 B
    ushort_t Al[STG][128][40];   // 30720 B
    ushort_t Bh[STG][KC][264];   // 50688 B
    ushort_t Bl[STG][KC][264];   // 50688 B
    float sred[2][128][2];
    float s_sh[2][128];
    float e_sh[2][128];
    float w_sh[2][2][64];
    float m_sh[2][2];
    float u_sh[2][2];
};

__global__ __launch_bounds__(256, 1)
void k_gemm_silu(const float* __restrict__ qw)
{
    extern __shared__ __align__(16) char smem_raw[];
    GSmem& S = *reinterpret_cast<GSmem*>(smem_raw);

    const int t    = threadIdx.x;
    const int warp = t >> 5, lane = t & 31;
    const int wm   = warp >> 2, wn = warp & 3;
    const int g    = lane >> 2, tg = lane & 3;
    const int m0   = blockIdx.x * 128;
    const int n0   = blockIdx.y * 256;

    float acc[4][8][4];
#pragma unroll
    for (int i = 0; i < 4; i++)
#pragma unroll
        for (int j = 0; j < 8; j++)
#pragma unroll
            for (int c = 0; c < 4; c++) acc[i][j][c] = 0.f;

    // load one KC=32 stage: A 128x32 (hi+lo), B 32x256 (hi+lo); 12 cp.async/thread
    auto load_stage = [&](int st, int bf) {
        const size_t k0 = (size_t)st * KC;
#pragma unroll
        for (int q = 0; q < 2; q++) {               // A: 512 chunks per plane
            int i = t + q * 256;
            int row = i >> 2, c16 = i & 3;
            size_t gi = (size_t)(m0 + row) * I_ + k0 + c16 * 8;
            cpa16(&S.Ah[bf][row][c16 * 8], g_ah + gi);
            cpa16(&S.Al[bf][row][c16 * 8], g_al + gi);
        }
#pragma unroll
        for (int q = 0; q < 4; q++) {               // B: 1024 chunks per plane
            int i = t + q * 256;
            int row = i >> 5, c16 = i & 31;
            size_t gi = (size_t)(k0 + row) * NTOT + n0 + c16 * 8;
            cpa16(&S.Bh[bf][row][c16 * 8], g_bh + gi);
            cpa16(&S.Bl[bf][row][c16 * 8], g_bl + gi);
        }
        asm volatile("cp.async.commit_group;");
    };

    const int arow = lane & 15;
    const int acol = (lane >> 4) * 8;

    load_stage(0, 0);
    load_stage(1, 1);

    int buf = 0;
#pragma unroll 1
    for (int s = 0; s < NST; s++) {
        if (s + 2 < NST) asm volatile("cp.async.wait_group 1;");
        else             asm volatile("cp.async.wait_group 0;");
        __syncthreads();
        if (s + 2 < NST) {
            int nb = buf + 2; if (nb >= STG) nb -= STG;
            load_stage(s + 2, nb);
        }
#pragma unroll
        for (int ks = 0; ks < 2; ks++) {
            uint32_t afh[4][4], afl[4][4];
#pragma unroll
            for (int it = 0; it < 4; it++) {
                ldsm_x4(afh[it], &S.Ah[buf][wm * 64 + it * 16 + arow][ks * 16 + acol]);
                ldsm_x4(afl[it], &S.Al[buf][wm * 64 + it * 16 + arow][ks * 16 + acol]);
            }
#pragma unroll
            for (int jt = 0; jt < 8; jt++) {
                uint32_t bfh[2], bfl[2];
                ldsm_x2t(bfh, &S.Bh[buf][ks * 16 + arow][wn * 64 + jt * 8]);
                ldsm_x2t(bfl, &S.Bl[buf][ks * 16 + arow][wn * 64 + jt * 8]);
#pragma unroll
                for (int it = 0; it < 4; it++) {
                    mma16816(acc[it][jt], afh[it], bfh);
                    mma16816(acc[it][jt], afh[it], bfl);
                    mma16816(acc[it][jt], afl[it], bfh);
                }
            }
        }
        if (++buf >= STG) buf = 0;
    }
    __syncthreads();

    // ---- epilogue: silu, v store, score partials ----
#pragma unroll
    for (int it = 0; it < 4; it++)
#pragma unroll
        for (int jt = 0; jt < 8; jt++)
#pragma unroll
            for (int c = 0; c < 4; c++) {
                float x = acc[it][jt][c];
                acc[it][jt][c] = __fdividef(x, 1.f + __expf(-x));
            }

    const int head_l = wn >> 1;
    const int head_g = blockIdx.y * 2 + head_l;
    float ps[4][2];
#pragma unroll
    for (int it = 0; it < 4; it++) { ps[it][0] = 0.f; ps[it][1] = 0.f; }

#pragma unroll
    for (int it = 0; it < 4; it++) {
        const int row0 = m0 + wm * 64 + it * 16 + g;
#pragma unroll
        for (int jt = 0; jt < 8; jt++) {
            const int d  = (wn & 1) * 32 + jt * 4 + tg;
            const float qv = qw[head_g * D_ + d];
            ps[it][0] += qv * acc[it][jt][0];
            ps[it][1] += qv * acc[it][jt][2];
            g_v[((size_t)row0       * H_ + head_g) * D_ + d] = acc[it][jt][1];
            g_v[((size_t)(row0 + 8) * H_ + head_g) * D_ + d] = acc[it][jt][3];
        }
    }
#pragma unroll
    for (int it = 0; it < 4; it++)
#pragma unroll
        for (int hh = 0; hh < 2; hh++) {
            float v = ps[it][hh];
            v += __shfl_xor_sync(0xffffffffu, v, 1);
            v += __shfl_xor_sync(0xffffffffu, v, 2);
            ps[it][hh] = v;
        }
    if (tg == 0) {
#pragma unroll
        for (int it = 0; it < 4; it++) {
            S.sred[head_l][wm * 64 + it * 16 + g    ][wn & 1] = ps[it][0];
            S.sred[head_l][wm * 64 + it * 16 + g + 8][wn & 1] = ps[it][1];
        }
    }
    __syncthreads();

    // s per (head, row)
    {
        const int hl  = t >> 7;
        const int row = t & 127;
        float s = S.sred[hl][row][0] + S.sred[hl][row][1];
        g_s[(size_t)(m0 + row) * H_ + blockIdx.y * 2 + hl] = s;
        S.s_sh[hl][row] = s;
    }
    __syncthreads();

    // per-chunk (64-row half) max + expsum: warps 0,1 (one head each)
    if (warp < 2) {
#pragma unroll
        for (int half = 0; half < 2; half++) {
            float s0 = S.s_sh[warp][half * 64 + lane];
            float s1 = S.s_sh[warp][half * 64 + 32 + lane];
            float mx = fmaxf(s0, s1);
#pragma unroll
            for (int o = 16; o >= 1; o >>= 1)
                mx = fmaxf(mx, __shfl_xor_sync(0xffffffffu, mx, o));
            float e0 = __expf(s0 - mx);
            float e1 = __expf(s1 - mx);
            S.e_sh[warp][half * 64 + lane]      = e0;
            S.e_sh[warp][half * 64 + 32 + lane] = e1;
            float us = e0 + e1;
#pragma unroll
            for (int o = 16; o >= 1; o >>= 1)
                us += __shfl_xor_sync(0xffffffffu, us, o);
            if (lane == 0) { S.m_sh[warp][half] = mx; S.u_sh[warp][half] = us; }
        }
    }
    __syncthreads();

    // chunk w: each warp covers rows wm*64..+63 == chunk half wm
    {
        float pw[8];
#pragma unroll
        for (int jt = 0; jt < 8; jt++) pw[jt] = 0.f;
#pragma unroll
        for (int it = 0; it < 4; it++) {
            const int r0 = wm * 64 + it * 16 + g;
            float e0 = S.e_sh[head_l][r0];
            float e1 = S.e_sh[head_l][r0 + 8];
#pragma unroll
            for (int jt = 0; jt < 8; jt++)
                pw[jt] = fmaf(e0, acc[it][jt][1], fmaf(e1, acc[it][jt][3], pw[jt]));
        }
#pragma unroll
        for (int jt = 0; jt < 8; jt++) {
            float v = pw[jt];
            v += __shfl_xor_sync(0xffffffffu, v, 4);
            v += __shfl_xor_sync(0xffffffffu, v, 8);
            v += __shfl_xor_sync(0xffffffffu, v, 16);
            pw[jt] = v;
        }
        if (g == 0) {
#pragma unroll
            for (int jt = 0; jt < 8; jt++)
                S.w_sh[head_l][wm][(wn & 1) * 32 + jt * 4 + tg] = pw[jt];
        }
    }
    __syncthreads();

    // write chunk aggregates
    {
        const int hl   = t >> 7;
        const int half = (t >> 6) & 1;
        const int d    = t & 63;
        const int hg   = blockIdx.y * 2 + hl;
        const int b    = m0 >> 12;
        const int cb   = (m0 & 4095) >> 6;
        const int idx  = (b * H_ + hg) * NC + cb + half;
        g_aw[idx * D_ + d] = S.w_sh[hl][half][d];
        if (d == 0) { g_am[idx] = S.m_sh[hl][half]; g_au[idx] = S.u_sh[hl][half]; }
    }
}

// ---------------------------------------------------------------------------
// Kernel 3: exclusive prefix over chunk aggregates.
// ---------------------------------------------------------------------------
__global__ __launch_bounds__(64)
void k_prefix()
{
    const int bh = blockIdx.x;
    const int d  = threadIdx.x;
    float m = -1e30f, u = 0.f, w = 0.f;
    for (int c = 0; c < NC; c++) {
        const int idx = bh * NC + c;
        if (d == 0) { g_pm[idx] = m; g_pu[idx] = u; }
        g_pw[idx * D_ + d] = w;
        float am = g_am[idx];
        float au = g_au[idx];
        float aw = g_aw[idx * D_ + d];
        float mn = fmaxf(m, am);
        float ea = __expf(m  - mn);
        float eb = __expf(am - mn);
        u = u * ea + au * eb;
        w = w * ea + aw * eb;
        m = mn;
    }
}

// ---------------------------------------------------------------------------
// Kernel 4: apply — 4 heads per block (256 threads), CH=64.
// ---------------------------------------------------------------------------
__global__ __launch_bounds__(256)
void k_apply(float* __restrict__ out)
{
    const int c   = blockIdx.x;
    const int bh0 = blockIdx.y * 4;
    const int t   = threadIdx.x;
    const int hh  = t >> 6;
    const int d   = t & 63;
    const int bh  = bh0 + hh;
    const int b   = bh >> 4;
    const int h   = bh & 15;
    const int t0  = c * CH;

    __shared__ float ssh[4][CH];
    {
        const int i  = t >> 2;
        const int hx = t & 3;
        ssh[hx][i] = g_s[(size_t)(b * T_ + t0 + i) * H_ + ((bh0 + hx) & 15)];
    }
    __syncthreads();

    const int idx = bh * NC + c;
    float m = g_pm[idx];
    float u = g_pu[idx];
    float w = g_pw[idx * D_ + d];

    const float* vp = g_v + ((size_t)(b * T_ + t0) * H_ + h) * D_ + d;
    float*       op = out + ((size_t)(b * T_ + t0) * H_ + h) * D_ + d;

#pragma unroll 4
    for (int i = 0; i < CH; i++) {
        float s  = ssh[hh][i];
        float mn = fmaxf(m, s);
        float ea = __expf(m - mn);
        float eb = __expf(s - mn);
        u = u * ea + eb;
        w = fmaf(w, ea, vp[(size_t)i * (H_ * D_)] * eb);
        m = mn;
        op[(size_t)i * (H_ * D_)] = __fdividef(w, u);
    }
}

// ---------------------------------------------------------------------------
extern "C" void kernel_launch(void* const* d_in, const int* in_sizes, int n_in,
                              void* d_out, int out_size)
{
    const float* inp = (const float*)d_in[0];   // (B,T,I)
    const float* kvw = (const float*)d_in[1];   // (I,H,D,2)
    const float* qw  = (const float*)d_in[2];   // (H,D)
    float* out = (float*)d_out;                 // (B,T,H,D)

    static int init = 0;
    if (!init) {
        cudaFuncSetAttribute(k_gemm_silu,
                             cudaFuncAttributeMaxDynamicSharedMemorySize,
                             (int)sizeof(GSmem));
        init = 1;
    }

    const int nsplit = (int)((NA4 + NB4 + 255) / 256);
    k_split<<<nsplit, 256>>>(inp, kvw);
    k_gemm_silu<<<dim3(M_ / 128, NTOT / 256), 256, sizeof(GSmem)>>>(qw);
    k_prefix<<<NBH, 64>>>();
    k_apply <<<dim3(NC, NBH / 4), 256>>>(out);
}

// round 8
// speedup vs baseline: 4.6141x; 1.3131x over previous
#include <cuda_runtime.h>
#include <cuda_fp16.h>
#include <cstdint>

#define B_   4
#define T_   4096
#define I_   1024
#define H_   16
#define D_   64
#define M_   (B_ * T_)        // 16384 rows (b,t)
#define NTOT 2048             // total N columns = H * 128
#define CH   64               // scan chunk length
#define NC   (T_ / CH)        // 64 chunks
#define NBH  (B_ * H_)        // 64 (b,h) pairs

#define KC   32               // K per pipeline stage
#define NST  (I_ / KC)        // 32 stages
#define STG  4                // ring depth

// ---------------- scratch (device globals: allocation-free) ----------------
__device__ __align__(16) __half g_ah[(size_t)M_ * I_];   // 32 MB  A hi
__device__ __align__(16) __half g_al[(size_t)M_ * I_];   // 32 MB  A lo
__device__ __align__(16) __half g_b [(size_t)I_ * NTOT]; // 4 MB   B [K][N] fp16
__device__ __align__(16) float g_v [ (size_t)M_ * H_ * D_ ]; // 64 MB
__device__ __align__(16) float g_s [ (size_t)M_ * H_ ];      // 1 MB
__device__ float g_am[ NBH * NC ];
__device__ float g_au[ NBH * NC ];
__device__ float g_aw[ NBH * NC * D_ ];
__device__ float g_pm[ NBH * NC ];
__device__ float g_pu[ NBH * NC ];
__device__ float g_pw[ NBH * NC * D_ ];

// ---------------- helpers ----------------
__device__ __forceinline__ void ldsm_x4(uint32_t* r, const void* p) {
    uint32_t a = (uint32_t)__cvta_generic_to_shared(p);
    asm volatile("ldmatrix.sync.aligned.m8n8.x4.shared.b16 {%0,%1,%2,%3}, [%4];"
                 : "=r"(r[0]), "=r"(r[1]), "=r"(r[2]), "=r"(r[3]) : "r"(a));
}
__device__ __forceinline__ void ldsm_x2t(uint32_t* r, const void* p) {
    uint32_t a = (uint32_t)__cvta_generic_to_shared(p);
    asm volatile("ldmatrix.sync.aligned.m8n8.x2.trans.shared.b16 {%0,%1}, [%2];"
                 : "=r"(r[0]), "=r"(r[1]) : "r"(a));
}
__device__ __forceinline__ void mma16816(float* c, const uint32_t* a, const uint32_t* b) {
    asm volatile(
        "mma.sync.aligned.m16n8k16.row.col.f32.f16.f16.f32 "
        "{%0,%1,%2,%3}, {%4,%5,%6,%7}, {%8,%9}, {%0,%1,%2,%3};"
        : "+f"(c[0]), "+f"(c[1]), "+f"(c[2]), "+f"(c[3])
        : "r"(a[0]), "r"(a[1]), "r"(a[2]), "r"(a[3]), "r"(b[0]), "r"(b[1]));
}
__device__ __forceinline__ void cpa16(void* dst, const void* src) {
    uint32_t d = (uint32_t)__cvta_generic_to_shared(dst);
    asm volatile("cp.async.cg.shared.global [%0], [%1], 16;" :: "r"(d), "l"(src));
}
__device__ __forceinline__ uint32_t pack2h(__half a, __half b) {
    return (uint32_t)__half_as_ushort(a) | ((uint32_t)__half_as_ushort(b) << 16);
}

// ---------------------------------------------------------------------------
// Kernel 0: one-time split: A fp32 -> (fp16 hi, fp16 lo); B fp32 -> fp16.
// ---------------------------------------------------------------------------
#define NA4 ((size_t)M_ * I_ / 4)
#define NB4 ((size_t)I_ * NTOT / 4)
__global__ __launch_bounds__(256)
void k_split(const float* __restrict__ inp, const float* __restrict__ kvw)
{
    size_t i = (size_t)blockIdx.x * 256 + threadIdx.x;
    if (i < NA4) {
        float4 x = ((const float4*)inp)[i];
        float xv[4] = {x.x, x.y, x.z, x.w};
        __half h[4], l[4];
#pragma unroll
        for (int p = 0; p < 4; p++) {
            h[p] = __float2half_rn(xv[p]);
            l[p] = __float2half_rn(xv[p] - __half2float(h[p]));
        }
        ((uint2*)g_ah)[i] = make_uint2(pack2h(h[0], h[1]), pack2h(h[2], h[3]));
        ((uint2*)g_al)[i] = make_uint2(pack2h(l[0], l[1]), pack2h(l[2], l[3]));
    } else if (i < NA4 + NB4) {
        size_t o = i - NA4;
        float4 x = ((const float4*)kvw)[o];
        ((uint2*)g_b)[o] = make_uint2(
            pack2h(__float2half_rn(x.x), __float2half_rn(x.y)),
            pack2h(__float2half_rn(x.z), __float2half_rn(x.w)));
    }
}

// ---------------------------------------------------------------------------
// Kernel 1: fp16 mma.sync GEMM (2-pass split-A) + silu + score + v-store
//           + fused per-chunk scan aggregates.
// Tile 128x256 (2 heads), 8 warps (2x4), KC=32, 4-stage cp.async ring.
// ---------------------------------------------------------------------------
struct GSmem {
    __half Ah[STG][128][40];   // 40960 B
    __half Al[STG][128][40];   // 40960 B
    __half Bs[STG][KC][264];   // 67584 B
    float sred[2][128][2];
    float s_sh[2][128];
    float e_sh[2][128];
    float w_sh[2][2][64];
    float m_sh[2][2];
    float u_sh[2][2];
};

__global__ __launch_bounds__(256, 1)
void k_gemm_silu(const float* __restrict__ qw)
{
    extern __shared__ __align__(16) char smem_raw[];
    GSmem& S = *reinterpret_cast<GSmem*>(smem_raw);

    const int t    = threadIdx.x;
    const int warp = t >> 5, lane = t & 31;
    const int wm   = warp >> 2, wn = warp & 3;
    const int g    = lane >> 2, tg = lane & 3;
    const int m0   = blockIdx.x * 128;
    const int n0   = blockIdx.y * 256;

    float acc[4][8][4];
#pragma unroll
    for (int i = 0; i < 4; i++)
#pragma unroll
        for (int j = 0; j < 8; j++)
#pragma unroll
            for (int c = 0; c < 4; c++) acc[i][j][c] = 0.f;

    // one KC=32 stage: A 128x32 hi+lo (4 chunks/thread), B 32x256 (4/thread)
    auto load_stage = [&](int st, int bf) {
        const size_t k0 = (size_t)st * KC;
#pragma unroll
        for (int q = 0; q < 2; q++) {
            int i = t + q * 256;
            int row = i >> 2, c16 = i & 3;
            size_t gi = (size_t)(m0 + row) * I_ + k0 + c16 * 8;
            cpa16(&S.Ah[bf][row][c16 * 8], g_ah + gi);
            cpa16(&S.Al[bf][row][c16 * 8], g_al + gi);
        }
#pragma unroll
        for (int q = 0; q < 4; q++) {
            int i = t + q * 256;
            int row = i >> 5, c16 = i & 31;
            size_t gi = (size_t)(k0 + row) * NTOT + n0 + c16 * 8;
            cpa16(&S.Bs[bf][row][c16 * 8], g_b + gi);
        }
        asm volatile("cp.async.commit_group;");
    };

    const int arow = lane & 15;
    const int acol = (lane >> 4) * 8;

    load_stage(0, 0);
    load_stage(1, 1);
    load_stage(2, 2);

#pragma unroll 1
    for (int s = 0; s < NST; s++) {
        const int buf = s & 3;
        if (s <= NST - 3)      asm volatile("cp.async.wait_group 2;");
        else if (s == NST - 2) asm volatile("cp.async.wait_group 1;");
        else                   asm volatile("cp.async.wait_group 0;");
        __syncthreads();
        if (s + 3 < NST) load_stage(s + 3, (s + 3) & 3);

#pragma unroll
        for (int ks = 0; ks < 2; ks++) {
            uint32_t afh[4][4], afl[4][4];
#pragma unroll
            for (int it = 0; it < 4; it++) {
                ldsm_x4(afh[it], &S.Ah[buf][wm * 64 + it * 16 + arow][ks * 16 + acol]);
                ldsm_x4(afl[it], &S.Al[buf][wm * 64 + it * 16 + arow][ks * 16 + acol]);
            }
#pragma unroll
            for (int jt = 0; jt < 8; jt++) {
                uint32_t bf2[2];
                ldsm_x2t(bf2, &S.Bs[buf][ks * 16 + arow][wn * 64 + jt * 8]);
#pragma unroll
                for (int it = 0; it < 4; it++) {
                    mma16816(acc[it][jt], afh[it], bf2);
                    mma16816(acc[it][jt], afl[it], bf2);
                }
            }
        }
    }
    __syncthreads();

    // ---- epilogue: silu, v store, score partials ----
#pragma unroll
    for (int it = 0; it < 4; it++)
#pragma unroll
        for (int jt = 0; jt < 8; jt++)
#pragma unroll
            for (int c = 0; c < 4; c++) {
                float x = acc[it][jt][c];
                acc[it][jt][c] = __fdividef(x, 1.f + __expf(-x));
            }

    const int head_l = wn >> 1;
    const int head_g = blockIdx.y * 2 + head_l;
    float ps[4][2];
#pragma unroll
    for (int it = 0; it < 4; it++) { ps[it][0] = 0.f; ps[it][1] = 0.f; }

#pragma unroll
    for (int it = 0; it < 4; it++) {
        const int row0 = m0 + wm * 64 + it * 16 + g;
#pragma unroll
        for (int jt = 0; jt < 8; jt++) {
            const int d  = (wn & 1) * 32 + jt * 4 + tg;
            const float qv = qw[head_g * D_ + d];
            ps[it][0] += qv * acc[it][jt][0];
            ps[it][1] += qv * acc[it][jt][2];
            g_v[((size_t)row0       * H_ + head_g) * D_ + d] = acc[it][jt][1];
            g_v[((size_t)(row0 + 8) * H_ + head_g) * D_ + d] = acc[it][jt][3];
        }
    }
#pragma unroll
    for (int it = 0; it < 4; it++)
#pragma unroll
        for (int hh = 0; hh < 2; hh++) {
            float v = ps[it][hh];
            v += __shfl_xor_sync(0xffffffffu, v, 1);
            v += __shfl_xor_sync(0xffffffffu, v, 2);
            ps[it][hh] = v;
        }
    if (tg == 0) {
#pragma unroll
        for (int it = 0; it < 4; it++) {
            S.sred[head_l][wm * 64 + it * 16 + g    ][wn & 1] = ps[it][0];
            S.sred[head_l][wm * 64 + it * 16 + g + 8][wn & 1] = ps[it][1];
        }
    }
    __syncthreads();

    // s per (head, row)
    {
        const int hl  = t >> 7;
        const int row = t & 127;
        float s = S.sred[hl][row][0] + S.sred[hl][row][1];
        g_s[(size_t)(m0 + row) * H_ + blockIdx.y * 2 + hl] = s;
        S.s_sh[hl][row] = s;
    }
    __syncthreads();

    // per-chunk (64-row half) max + expsum: warps 0,1 (one head each)
    if (warp < 2) {
#pragma unroll
        for (int half = 0; half < 2; half++) {
            float s0 = S.s_sh[warp][half * 64 + lane];
            float s1 = S.s_sh[warp][half * 64 + 32 + lane];
            float mx = fmaxf(s0, s1);
#pragma unroll
            for (int o = 16; o >= 1; o >>= 1)
                mx = fmaxf(mx, __shfl_xor_sync(0xffffffffu, mx, o));
            float e0 = __expf(s0 - mx);
            float e1 = __expf(s1 - mx);
            S.e_sh[warp][half * 64 + lane]      = e0;
            S.e_sh[warp][half * 64 + 32 + lane] = e1;
            float us = e0 + e1;
#pragma unroll
            for (int o = 16; o >= 1; o >>= 1)
                us += __shfl_xor_sync(0xffffffffu, us, o);
            if (lane == 0) { S.m_sh[warp][half] = mx; S.u_sh[warp][half] = us; }
        }
    }
    __syncthreads();

    // chunk w: each warp covers rows wm*64..+63 == chunk half wm
    {
        float pw[8];
#pragma unroll
        for (int jt = 0; jt < 8; jt++) pw[jt] = 0.f;
#pragma unroll
        for (int it = 0; it < 4; it++) {
            const int r0 = wm * 64 + it * 16 + g;
            float e0 = S.e_sh[head_l][r0];
            float e1 = S.e_sh[head_l][r0 + 8];
#pragma unroll
            for (int jt = 0; jt < 8; jt++)
                pw[jt] = fmaf(e0, acc[it][jt][1], fmaf(e1, acc[it][jt][3], pw[jt]));
        }
#pragma unroll
        for (int jt = 0; jt < 8; jt++) {
            float v = pw[jt];
            v += __shfl_xor_sync(0xffffffffu, v, 4);
            v += __shfl_xor_sync(0xffffffffu, v, 8);
            v += __shfl_xor_sync(0xffffffffu, v, 16);
            pw[jt] = v;
        }
        if (g == 0) {
#pragma unroll
            for (int jt = 0; jt < 8; jt++)
                S.w_sh[head_l][wm][(wn & 1) * 32 + jt * 4 + tg] = pw[jt];
        }
    }
    __syncthreads();

    // write chunk aggregates
    {
        const int hl   = t >> 7;
        const int half = (t >> 6) & 1;
        const int d    = t & 63;
        const int hg   = blockIdx.y * 2 + hl;
        const int b    = m0 >> 12;
        const int cb   = (m0 & 4095) >> 6;
        const int idx  = (b * H_ + hg) * NC + cb + half;
        g_aw[idx * D_ + d] = S.w_sh[hl][half][d];
        if (d == 0) { g_am[idx] = S.m_sh[hl][half]; g_au[idx] = S.u_sh[hl][half]; }
    }
}

// ---------------------------------------------------------------------------
// Kernel 3: exclusive prefix over chunk aggregates.
// ---------------------------------------------------------------------------
__global__ __launch_bounds__(64)
void k_prefix()
{
    const int bh = blockIdx.x;
    const int d  = threadIdx.x;
    float m = -1e30f, u = 0.f, w = 0.f;
    for (int c = 0; c < NC; c++) {
        const int idx = bh * NC + c;
        if (d == 0) { g_pm[idx] = m; g_pu[idx] = u; }
        g_pw[idx * D_ + d] = w;
        float am = g_am[idx];
        float au = g_au[idx];
        float aw = g_aw[idx * D_ + d];
        float mn = fmaxf(m, am);
        float ea = __expf(m  - mn);
        float eb = __expf(am - mn);
        u = u * ea + au * eb;
        w = w * ea + aw * eb;
        m = mn;
    }
}

// ---------------------------------------------------------------------------
// Kernel 4: apply — 4 heads per block (256 threads), CH=64.
// ---------------------------------------------------------------------------
__global__ __launch_bounds__(256)
void k_apply(float* __restrict__ out)
{
    const int c   = blockIdx.x;
    const int bh0 = blockIdx.y * 4;
    const int t   = threadIdx.x;
    const int hh  = t >> 6;
    const int d   = t & 63;
    const int bh  = bh0 + hh;
    const int b   = bh >> 4;
    const int h   = bh & 15;
    const int t0  = c * CH;

    __shared__ float ssh[4][CH];
    {
        const int i  = t >> 2;
        const int hx = t & 3;
        ssh[hx][i] = g_s[(size_t)(b * T_ + t0 + i) * H_ + ((bh0 + hx) & 15)];
    }
    __syncthreads();

    const int idx = bh * NC + c;
    float m = g_pm[idx];
    float u = g_pu[idx];
    float w = g_pw[idx * D_ + d];

    const float* vp = g_v + ((size_t)(b * T_ + t0) * H_ + h) * D_ + d;
    float*       op = out + ((size_t)(b * T_ + t0) * H_ + h) * D_ + d;

#pragma unroll 4
    for (int i = 0; i < CH; i++) {
        float s  = ssh[hh][i];
        float mn = fmaxf(m, s);
        float ea = __expf(m - mn);
        float eb = __expf(s - mn);
        u = u * ea + eb;
        w = fmaf(w, ea, vp[(size_t)i * (H_ * D_)] * eb);
        m = mn;
        op[(size_t)i * (H_ * D_)] = __fdividef(w, u);
    }
}

// ---------------------------------------------------------------------------
extern "C" void kernel_launch(void* const* d_in, const int* in_sizes, int n_in,
                              void* d_out, int out_size)
{
    const float* inp = (const float*)d_in[0];   // (B,T,I)
    const float* kvw = (const float*)d_in[1];   // (I,H,D,2)
    const float* qw  = (const float*)d_in[2];   // (H,D)
    float* out = (float*)d_out;                 // (B,T,H,D)

    static int init = 0;
    if (!init) {
        cudaFuncSetAttribute(k_gemm_silu,
                             cudaFuncAttributeMaxDynamicSharedMemorySize,
                             (int)sizeof(GSmem));
        init = 1;
    }

    const int nsplit = (int)((NA4 + NB4 + 255) / 256);
    k_split<<<nsplit, 256>>>(inp, kvw);
    k_gemm_silu<<<dim3(M_ / 128, NTOT / 256), 256, sizeof(GSmem)>>>(qw);
    k_prefix<<<NBH, 64>>>();
    k_apply <<<dim3(NC, NBH / 4), 256>>>(out);
}

// round 10
// speedup vs baseline: 6.5239x; 1.4139x over previous
#include <cuda_runtime.h>
#include <cuda_fp16.h>
#include <cstdint>

#define B_   4
#define T_   4096
#define I_   1024
#define H_   16
#define D_   64
#define M_   (B_ * T_)        // 16384 rows (b,t)
#define NTOT 2048             // total N columns = H * 128
#define CH   64               // scan chunk length
#define NC   (T_ / CH)        // 64 chunks
#define NBH  (B_ * H_)        // 64 (b,h) pairs

#define KC   32               // K per pipeline stage
#define NST  (I_ / KC)        // 32 stages
#define STG  4                // ring depth

// ---------------- scratch (device globals: allocation-free) ----------------
__device__ __align__(16) __half g_a [(size_t)M_ * I_];   // 32 MB  A fp16
__device__ __align__(16) __half g_b [(size_t)I_ * NTOT]; // 4 MB   B [K][N] fp16
__device__ __align__(16) float g_v [ (size_t)M_ * H_ * D_ ]; // 64 MB
__device__ __align__(16) float g_s [ (size_t)M_ * H_ ];      // 1 MB
__device__ float g_am[ NBH * NC ];
__device__ float g_au[ NBH * NC ];
__device__ float g_aw[ NBH * NC * D_ ];
__device__ float g_pm[ NBH * NC ];
__device__ float g_pu[ NBH * NC ];
__device__ float g_pw[ NBH * NC * D_ ];

// ---------------- helpers ----------------
__device__ __forceinline__ void ldsm_x4(uint32_t* r, const void* p) {
    uint32_t a = (uint32_t)__cvta_generic_to_shared(p);
    asm volatile("ldmatrix.sync.aligned.m8n8.x4.shared.b16 {%0,%1,%2,%3}, [%4];"
                 : "=r"(r[0]), "=r"(r[1]), "=r"(r[2]), "=r"(r[3]) : "r"(a));
}
__device__ __forceinline__ void ldsm_x2t(uint32_t* r, const void* p) {
    uint32_t a = (uint32_t)__cvta_generic_to_shared(p);
    asm volatile("ldmatrix.sync.aligned.m8n8.x2.trans.shared.b16 {%0,%1}, [%2];"
                 : "=r"(r[0]), "=r"(r[1]) : "r"(a));
}
__device__ __forceinline__ void mma16816(float* c, const uint32_t* a, const uint32_t* b) {
    asm volatile(
        "mma.sync.aligned.m16n8k16.row.col.f32.f16.f16.f32 "
        "{%0,%1,%2,%3}, {%4,%5,%6,%7}, {%8,%9}, {%0,%1,%2,%3};"
        : "+f"(c[0]), "+f"(c[1]), "+f"(c[2]), "+f"(c[3])
        : "r"(a[0]), "r"(a[1]), "r"(a[2]), "r"(a[3]), "r"(b[0]), "r"(b[1]));
}
__device__ __forceinline__ void cpa16(void* dst, const void* src) {
    uint32_t d = (uint32_t)__cvta_generic_to_shared(dst);
    asm volatile("cp.async.cg.shared.global [%0], [%1], 16;" :: "r"(d), "l"(src));
}
__device__ __forceinline__ uint32_t pack2h(__half a, __half b) {
    return (uint32_t)__half_as_ushort(a) | ((uint32_t)__half_as_ushort(b) << 16);
}

// ---------------------------------------------------------------------------
// Kernel 0: one-time fp32 -> fp16 convert of A and B.
// ---------------------------------------------------------------------------
#define NA4 ((size_t)M_ * I_ / 4)
#define NB4 ((size_t)I_ * NTOT / 4)
__global__ __launch_bounds__(256)
void k_split(const float* __restrict__ inp, const float* __restrict__ kvw)
{
    size_t i = (size_t)blockIdx.x * 256 + threadIdx.x;
    const float4* src;
    __half* dst;
    size_t o;
    if (i < NA4)            { src = (const float4*)inp; dst = g_a; o = i; }
    else if (i < NA4 + NB4) { src = (const float4*)kvw; dst = g_b; o = i - NA4; }
    else return;
    float4 x = src[o];
    ((uint2*)dst)[o] = make_uint2(
        pack2h(__float2half_rn(x.x), __float2half_rn(x.y)),
        pack2h(__float2half_rn(x.z), __float2half_rn(x.w)));
}

// ---------------------------------------------------------------------------
// Kernel 1: fp16 mma.sync GEMM (1-pass) + silu + score + v-store
//           + fused per-chunk scan aggregates.
// Tile 128x256 (2 heads), 8 warps (2x4), KC=32, 4-stage cp.async ring.
// ---------------------------------------------------------------------------
struct GSmem {
    __half As[STG][128][40];   // 40960 B
    __half Bs[STG][KC][264];   // 67584 B
    float sred[2][128][2];
    float s_sh[2][128];
    float e_sh[2][128];
    float w_sh[2][2][64];
    float m_sh[2][2];
    float u_sh[2][2];
};

__global__ __launch_bounds__(256, 1)
void k_gemm_silu(const float* __restrict__ qw)
{
    extern __shared__ __align__(16) char smem_raw[];
    GSmem& S = *reinterpret_cast<GSmem*>(smem_raw);

    const int t    = threadIdx.x;
    const int warp = t >> 5, lane = t & 31;
    const int wm   = warp >> 2, wn = warp & 3;
    const int g    = lane >> 2, tg = lane & 3;
    const int m0   = blockIdx.x * 128;
    const int n0   = blockIdx.y * 256;

    float acc[4][8][4];
#pragma unroll
    for (int i = 0; i < 4; i++)
#pragma unroll
        for (int j = 0; j < 8; j++)
#pragma unroll
            for (int c = 0; c < 4; c++) acc[i][j][c] = 0.f;

    // one KC=32 stage: A 128x32 (2 chunks/thread), B 32x256 (4 chunks/thread)
    auto load_stage = [&](int st, int bf) {
        const size_t k0 = (size_t)st * KC;
#pragma unroll
        for (int q = 0; q < 2; q++) {
            int i = t + q * 256;
            int row = i >> 2, c16 = i & 3;
            size_t gi = (size_t)(m0 + row) * I_ + k0 + c16 * 8;
            cpa16(&S.As[bf][row][c16 * 8], g_a + gi);
        }
#pragma unroll
        for (int q = 0; q < 4; q++) {
            int i = t + q * 256;
            int row = i >> 5, c16 = i & 31;
            size_t gi = (size_t)(k0 + row) * NTOT + n0 + c16 * 8;
            cpa16(&S.Bs[bf][row][c16 * 8], g_b + gi);
        }
        asm volatile("cp.async.commit_group;");
    };

    const int arow = lane & 15;
    const int acol = (lane >> 4) * 8;

    load_stage(0, 0);
    load_stage(1, 1);
    load_stage(2, 2);

#pragma unroll 1
    for (int s = 0; s < NST; s++) {
        const int buf = s & 3;
        if (s <= NST - 3)      asm volatile("cp.async.wait_group 2;");
        else if (s == NST - 2) asm volatile("cp.async.wait_group 1;");
        else                   asm volatile("cp.async.wait_group 0;");
        __syncthreads();
        if (s + 3 < NST) load_stage(s + 3, (s + 3) & 3);

#pragma unroll
        for (int ks = 0; ks < 2; ks++) {
            uint32_t af[4][4];
#pragma unroll
            for (int it = 0; it < 4; it++)
                ldsm_x4(af[it], &S.As[buf][wm * 64 + it * 16 + arow][ks * 16 + acol]);
#pragma unroll
            for (int jt = 0; jt < 8; jt++) {
                uint32_t bf2[2];
                ldsm_x2t(bf2, &S.Bs[buf][ks * 16 + arow][wn * 64 + jt * 8]);
#pragma unroll
                for (int it = 0; it < 4; it++)
                    mma16816(acc[it][jt], af[it], bf2);
            }
        }
    }
    __syncthreads();

    // ---- epilogue: silu, v store, score partials ----
#pragma unroll
    for (int it = 0; it < 4; it++)
#pragma unroll
        for (int jt = 0; jt < 8; jt++)
#pragma unroll
            for (int c = 0; c < 4; c++) {
                float x = acc[it][jt][c];
                acc[it][jt][c] = __fdividef(x, 1.f + __expf(-x));
            }

    const int head_l = wn >> 1;
    const int head_g = blockIdx.y * 2 + head_l;
    float ps[4][2];
#pragma unroll
    for (int it = 0; it < 4; it++) { ps[it][0] = 0.f; ps[it][1] = 0.f; }

#pragma unroll
    for (int it = 0; it < 4; it++) {
        const int row0 = m0 + wm * 64 + it * 16 + g;
#pragma unroll
        for (int jt = 0; jt < 8; jt++) {
            const int d  = (wn & 1) * 32 + jt * 4 + tg;
            const float qv = qw[head_g * D_ + d];
            ps[it][0] += qv * acc[it][jt][0];
            ps[it][1] += qv * acc[it][jt][2];
            g_v[((size_t)row0       * H_ + head_g) * D_ + d] = acc[it][jt][1];
            g_v[((size_t)(row0 + 8) * H_ + head_g) * D_ + d] = acc[it][jt][3];
        }
    }
#pragma unroll
    for (int it = 0; it < 4; it++)
#pragma unroll
        for (int hh = 0; hh < 2; hh++) {
            float v = ps[it][hh];
            v += __shfl_xor_sync(0xffffffffu, v, 1);
            v += __shfl_xor_sync(0xffffffffu, v, 2);
            ps[it][hh] = v;
        }
    if (tg == 0) {
#pragma unroll
        for (int it = 0; it < 4; it++) {
            S.sred[head_l][wm * 64 + it * 16 + g    ][wn & 1] = ps[it][0];
            S.sred[head_l][wm * 64 + it * 16 + g + 8][wn & 1] = ps[it][1];
        }
    }
    __syncthreads();

    // s per (head, row)
    {
        const int hl  = t >> 7;
        const int row = t & 127;
        float s = S.sred[hl][row][0] + S.sred[hl][row][1];
        g_s[(size_t)(m0 + row) * H_ + blockIdx.y * 2 + hl] = s;
        S.s_sh[hl][row] = s;
    }
    __syncthreads();

    // per-chunk (64-row half) max + expsum: warps 0,1 (one head each)
    if (warp < 2) {
#pragma unroll
        for (int half = 0; half < 2; half++) {
            float s0 = S.s_sh[warp][half * 64 + lane];
            float s1 = S.s_sh[warp][half * 64 + 32 + lane];
            float mx = fmaxf(s0, s1);
#pragma unroll
            for (int o = 16; o >= 1; o >>= 1)
                mx = fmaxf(mx, __shfl_xor_sync(0xffffffffu, mx, o));
            float e0 = __expf(s0 - mx);
            float e1 = __expf(s1 - mx);
            S.e_sh[warp][half * 64 + lane]      = e0;
            S.e_sh[warp][half * 64 + 32 + lane] = e1;
            float us = e0 + e1;
#pragma unroll
            for (int o = 16; o >= 1; o >>= 1)
                us += __shfl_xor_sync(0xffffffffu, us, o);
            if (lane == 0) { S.m_sh[warp][half] = mx; S.u_sh[warp][half] = us; }
        }
    }
    __syncthreads();

    // chunk w: each warp covers rows wm*64..+63 == chunk half wm
    {
        float pw[8];
#pragma unroll
        for (int jt = 0; jt < 8; jt++) pw[jt] = 0.f;
#pragma unroll
        for (int it = 0; it < 4; it++) {
            const int r0 = wm * 64 + it * 16 + g;
            float e0 = S.e_sh[head_l][r0];
            float e1 = S.e_sh[head_l][r0 + 8];
#pragma unroll
            for (int jt = 0; jt < 8; jt++)
                pw[jt] = fmaf(e0, acc[it][jt][1], fmaf(e1, acc[it][jt][3], pw[jt]));
        }
#pragma unroll
        for (int jt = 0; jt < 8; jt++) {
            float v = pw[jt];
            v += __shfl_xor_sync(0xffffffffu, v, 4);
            v += __shfl_xor_sync(0xffffffffu, v, 8);
            v += __shfl_xor_sync(0xffffffffu, v, 16);
            pw[jt] = v;
        }
        if (g == 0) {
#pragma unroll
            for (int jt = 0; jt < 8; jt++)
                S.w_sh[head_l][wm][(wn & 1) * 32 + jt * 4 + tg] = pw[jt];
        }
    }
    __syncthreads();

    // write chunk aggregates
    {
        const int hl   = t >> 7;
        const int half = (t >> 6) & 1;
        const int d    = t & 63;
        const int hg   = blockIdx.y * 2 + hl;
        const int b    = m0 >> 12;
        const int cb   = (m0 & 4095) >> 6;
        const int idx  = (b * H_ + hg) * NC + cb + half;
        g_aw[idx * D_ + d] = S.w_sh[hl][half][d];
        if (d == 0) { g_am[idx] = S.m_sh[hl][half]; g_au[idx] = S.u_sh[hl][half]; }
    }
}

// ---------------------------------------------------------------------------
// Kernel 3: exclusive prefix over chunk aggregates.
// ---------------------------------------------------------------------------
__global__ __launch_bounds__(64)
void k_prefix()
{
    const int bh = blockIdx.x;
    const int d  = threadIdx.x;
    float m = -1e30f, u = 0.f, w = 0.f;
    for (int c = 0; c < NC; c++) {
        const int idx = bh * NC + c;
        if (d == 0) { g_pm[idx] = m; g_pu[idx] = u; }
        g_pw[idx * D_ + d] = w;
        float am = g_am[idx];
        float au = g_au[idx];
        float aw = g_aw[idx * D_ + d];
        float mn = fmaxf(m, am);
        float ea = __expf(m  - mn);
        float eb = __expf(am - mn);
        u = u * ea + au * eb;
        w = w * ea + aw * eb;
        m = mn;
    }
}

// ---------------------------------------------------------------------------
// Kernel 4: apply — 4 heads per block (256 threads), CH=64.
// ---------------------------------------------------------------------------
__global__ __launch_bounds__(256)
void k_apply(float* __restrict__ out)
{
    const int c   = blockIdx.x;
    const int bh0 = blockIdx.y * 4;
    const int t   = threadIdx.x;
    const int hh  = t >> 6;
    const int d   = t & 63;
    const int bh  = bh0 + hh;
    const int b   = bh >> 4;
    const int h   = bh & 15;
    const int t0  = c * CH;

    __shared__ float ssh[4][CH];
    {
        const int i  = t >> 2;
        const int hx = t & 3;
        ssh[hx][i] = g_s[(size_t)(b * T_ + t0 + i) * H_ + ((bh0 + hx) & 15)];
    }
    __syncthreads();

    const int idx = bh * NC + c;
    float m = g_pm[idx];
    float u = g_pu[idx];
    float w = g_pw[idx * D_ + d];

    const float* vp = g_v + ((size_t)(b * T_ + t0) * H_ + h) * D_ + d;
    float*       op = out + ((size_t)(b * T_ + t0) * H_ + h) * D_ + d;

#pragma unroll 4
    for (int i = 0; i < CH; i++) {
        float s  = ssh[hh][i];
        float mn = fmaxf(m, s);
        float ea = __expf(m - mn);
        float eb = __expf(s - mn);
        u = u * ea + eb;
        w = fmaf(w, ea, vp[(size_t)i * (H_ * D_)] * eb);
        m = mn;
        op[(size_t)i * (H_ * D_)] = __fdividef(w, u);
    }
}

// ---------------------------------------------------------------------------
extern "C" void kernel_launch(void* const* d_in, const int* in_sizes, int n_in,
                              void* d_out, int out_size)
{
    const float* inp = (const float*)d_in[0];   // (B,T,I)
    const float* kvw = (const float*)d_in[1];   // (I,H,D,2)
    const float* qw  = (const float*)d_in[2];   // (H,D)
    float* out = (float*)d_out;                 // (B,T,H,D)

    static int init = 0;
    if (!init) {
        cudaFuncSetAttribute(k_gemm_silu,
                             cudaFuncAttributeMaxDynamicSharedMemorySize,
                             (int)sizeof(GSmem));
        init = 1;
    }

    const int nsplit = (int)((NA4 + NB4 + 255) / 256);
    k_split<<<nsplit, 256>>>(inp, kvw);
    k_gemm_silu<<<dim3(M_ / 128, NTOT / 256), 256, sizeof(GSmem)>>>(qw);
    k_prefix<<<NBH, 64>>>();
    k_apply <<<dim3(NC, NBH / 4), 256>>>(out);
}